// round 1
// baseline (speedup 1.0000x reference)
#include <cuda_runtime.h>
#include <math.h>

#define BB  4
#define NSEQ 2048
#define CC  1024
#define HH  16
#define DD  64
#define MM  (BB*NSEQ)   // 8192 rows

// Scratch (allocation-free rule: __device__ globals)
__device__ float g_q[(size_t)MM*CC];
__device__ float g_k[(size_t)MM*CC];
__device__ float g_v[(size_t)MM*CC];
__device__ float g_o[(size_t)MM*CC];

// ---------------------------------------------------------------------------
// NT GEMM: C[M,N] = alpha * A[M,K] @ B[N,K]^T (+bias) (+sigmoid)
// 64x64 tile, BK=16, 256 threads, 4x4 per-thread microtile.
// All dims are multiples of 64/16 in this problem -> no bounds checks.
// ---------------------------------------------------------------------------
template<int SIG>
__global__ void __launch_bounds__(256)
gemm_nt_kernel(const float* __restrict__ A, int lda,
               const float* __restrict__ B, int ldb,
               float* __restrict__ C, int ldc,
               int K, float alpha, const float* __restrict__ bias)
{
    __shared__ float As[16][65];
    __shared__ float Bs[16][65];
    const int t  = threadIdx.x;
    const int tx = t & 15;
    const int ty = t >> 4;
    const int bm = blockIdx.y * 64;
    const int bn = blockIdx.x * 64;
    const float* Ab = A + (size_t)bm * lda;
    const float* Bb = B + (size_t)bn * ldb;
    const int lm = t >> 2;          // row 0..63
    const int lk = (t & 3) << 2;    // k offset 0,4,8,12
    float acc[4][4] = {};
    for (int k0 = 0; k0 < K; k0 += 16) {
        float4 av = *(const float4*)(Ab + (size_t)lm * lda + k0 + lk);
        float4 bv = *(const float4*)(Bb + (size_t)lm * ldb + k0 + lk);
        As[lk+0][lm]=av.x; As[lk+1][lm]=av.y; As[lk+2][lm]=av.z; As[lk+3][lm]=av.w;
        Bs[lk+0][lm]=bv.x; Bs[lk+1][lm]=bv.y; Bs[lk+2][lm]=bv.z; Bs[lk+3][lm]=bv.w;
        __syncthreads();
        #pragma unroll
        for (int k = 0; k < 16; k++) {
            float a[4], b[4];
            #pragma unroll
            for (int i = 0; i < 4; i++) a[i] = As[k][ty*4+i];
            #pragma unroll
            for (int j = 0; j < 4; j++) b[j] = Bs[k][tx*4+j];
            #pragma unroll
            for (int i = 0; i < 4; i++)
                #pragma unroll
                for (int j = 0; j < 4; j++)
                    acc[i][j] = fmaf(a[i], b[j], acc[i][j]);
        }
        __syncthreads();
    }
    #pragma unroll
    for (int i = 0; i < 4; i++) {
        const int row = bm + ty*4 + i;
        #pragma unroll
        for (int j = 0; j < 4; j++) {
            const int col = bn + tx*4 + j;
            float v = acc[i][j] * alpha;
            if (SIG) v = 1.f / (1.f + __expf(-v));
            if (bias) v += bias[col];
            C[(size_t)row * ldc + col] = v;
        }
    }
}

// ---------------------------------------------------------------------------
// Per-head scores: attn[z,n,m] = sigmoid(scale * sum_d Q[b,n,hD+d]*K[b,m,hD+d])
// z = b*H+h in blockIdx.z. K dim = 64.
// ---------------------------------------------------------------------------
__global__ void __launch_bounds__(256)
scores_kernel(const float* __restrict__ Q, const float* __restrict__ Kp,
              float* __restrict__ attn)
{
    const int z = blockIdx.z;
    const int b = z / HH;
    const int h = z % HH;
    const size_t off = (size_t)b * NSEQ * CC + (size_t)h * DD;
    __shared__ float As[16][65];
    __shared__ float Bs[16][65];
    const int t  = threadIdx.x;
    const int tx = t & 15;
    const int ty = t >> 4;
    const int bm = blockIdx.y * 64;
    const int bn = blockIdx.x * 64;
    const float* Ab = Q  + off + (size_t)bm * CC;
    const float* Bb = Kp + off + (size_t)bn * CC;
    float* Cb = attn + (size_t)z * NSEQ * NSEQ;
    const int lm = t >> 2;
    const int lk = (t & 3) << 2;
    float acc[4][4] = {};
    for (int k0 = 0; k0 < DD; k0 += 16) {
        float4 av = *(const float4*)(Ab + (size_t)lm * CC + k0 + lk);
        float4 bv = *(const float4*)(Bb + (size_t)lm * CC + k0 + lk);
        As[lk+0][lm]=av.x; As[lk+1][lm]=av.y; As[lk+2][lm]=av.z; As[lk+3][lm]=av.w;
        Bs[lk+0][lm]=bv.x; Bs[lk+1][lm]=bv.y; Bs[lk+2][lm]=bv.z; Bs[lk+3][lm]=bv.w;
        __syncthreads();
        #pragma unroll
        for (int k = 0; k < 16; k++) {
            float a[4], b2[4];
            #pragma unroll
            for (int i = 0; i < 4; i++) a[i]  = As[k][ty*4+i];
            #pragma unroll
            for (int j = 0; j < 4; j++) b2[j] = Bs[k][tx*4+j];
            #pragma unroll
            for (int i = 0; i < 4; i++)
                #pragma unroll
                for (int j = 0; j < 4; j++)
                    acc[i][j] = fmaf(a[i], b2[j], acc[i][j]);
        }
        __syncthreads();
    }
    const float scale = 0.125f;  // 64^-0.5
    #pragma unroll
    for (int i = 0; i < 4; i++) {
        const int row = bm + ty*4 + i;
        #pragma unroll
        for (int j = 0; j < 4; j++) {
            const int col = bn + tx*4 + j;
            float v = acc[i][j] * scale;
            v = 1.f / (1.f + __expf(-v));
            Cb[(size_t)row * NSEQ + col] = v;
        }
    }
}

// ---------------------------------------------------------------------------
// Per-head attn @ V (NN): O[b,n,hD+d] = sum_m attn[z,n,m] * V[b,m,hD+d]
// N dim = 64 (one tile wide). K = 2048.
// ---------------------------------------------------------------------------
__global__ void __launch_bounds__(256)
av_kernel(const float* __restrict__ attn, const float* __restrict__ V,
          float* __restrict__ O)
{
    const int z = blockIdx.z;
    const int b = z / HH;
    const int h = z % HH;
    const size_t off = (size_t)b * NSEQ * CC + (size_t)h * DD;
    __shared__ float As[16][65];
    __shared__ float Bs[16][65];
    const int t  = threadIdx.x;
    const int tx = t & 15;
    const int ty = t >> 4;
    const int bm = blockIdx.y * 64;
    const float* Ab = attn + (size_t)z * NSEQ * NSEQ + (size_t)bm * NSEQ;
    const float* Bb = V + off;
    float* Cb = O + off + (size_t)bm * CC;
    const int lma = t >> 2;          // A row
    const int lka = (t & 3) << 2;    // A k
    const int lkb = t >> 4;          // B k row (0..15)
    const int lnb = (t & 15) << 2;   // B col 0..60
    float acc[4][4] = {};
    for (int k0 = 0; k0 < NSEQ; k0 += 16) {
        float4 av = *(const float4*)(Ab + (size_t)lma * NSEQ + k0 + lka);
        float4 bv = *(const float4*)(Bb + (size_t)(k0 + lkb) * CC + lnb);
        As[lka+0][lma]=av.x; As[lka+1][lma]=av.y; As[lka+2][lma]=av.z; As[lka+3][lma]=av.w;
        Bs[lkb][lnb+0]=bv.x; Bs[lkb][lnb+1]=bv.y; Bs[lkb][lnb+2]=bv.z; Bs[lkb][lnb+3]=bv.w;
        __syncthreads();
        #pragma unroll
        for (int k = 0; k < 16; k++) {
            float a[4], b2[4];
            #pragma unroll
            for (int i = 0; i < 4; i++) a[i]  = As[k][ty*4+i];
            #pragma unroll
            for (int j = 0; j < 4; j++) b2[j] = Bs[k][tx*4+j];
            #pragma unroll
            for (int i = 0; i < 4; i++)
                #pragma unroll
                for (int j = 0; j < 4; j++)
                    acc[i][j] = fmaf(a[i], b2[j], acc[i][j]);
        }
        __syncthreads();
    }
    #pragma unroll
    for (int i = 0; i < 4; i++) {
        const int row = ty*4 + i;
        #pragma unroll
        for (int j = 0; j < 4; j++) {
            const int col = tx*4 + j;
            Cb[(size_t)row * CC + col] = acc[i][j];
        }
    }
}

// ---------------------------------------------------------------------------
extern "C" void kernel_launch(void* const* d_in, const int* in_sizes, int n_in,
                              void* d_out, int out_size)
{
    const float* x_q = (const float*)d_in[0];
    const float* x_k = (const float*)d_in[1];
    const float* x_v = (const float*)d_in[2];
    const float* Wq  = (const float*)d_in[3];
    const float* Wk  = (const float*)d_in[4];
    const float* Wv  = (const float*)d_in[5];
    const float* Wp  = (const float*)d_in[6];
    const float* bp  = (const float*)d_in[7];

    float *q, *k, *v, *o;
    cudaGetSymbolAddress((void**)&q, g_q);
    cudaGetSymbolAddress((void**)&k, g_k);
    cudaGetSymbolAddress((void**)&v, g_v);
    cudaGetSymbolAddress((void**)&o, g_o);

    float* out  = (float*)d_out;                       // [B,N,C]
    float* attn = out + (size_t)MM * CC;               // [B,H,N,N]

    dim3 blk(256);
    dim3 gProj(CC/64, MM/64);          // 16 x 128

    // QKV projections: y = x @ W^T
    gemm_nt_kernel<0><<<gProj, blk>>>(x_q, CC, Wq, CC, q, CC, CC, 1.f, nullptr);
    gemm_nt_kernel<0><<<gProj, blk>>>(x_k, CC, Wk, CC, k, CC, CC, 1.f, nullptr);
    gemm_nt_kernel<0><<<gProj, blk>>>(x_v, CC, Wv, CC, v, CC, CC, 1.f, nullptr);

    // attn = sigmoid(Q K^T / sqrt(D)) per (b,h)
    scores_kernel<<<dim3(NSEQ/64, NSEQ/64, BB*HH), blk>>>(q, k, attn);

    // O = attn @ V per (b,h)
    av_kernel<<<dim3(1, NSEQ/64, BB*HH), blk>>>(attn, v, o);

    // out = O @ Wp^T + bp
    gemm_nt_kernel<0><<<gProj, blk>>>(o, CC, Wp, CC, out, CC, CC, 1.f, bp);
}